// round 2
// baseline (speedup 1.0000x reference)
#include <cuda_runtime.h>

#define S_LEN 2048
#define EMB 1024
#define HEADS 16
#define HDIM 64
#define BATCH 2
#define QKV_F (3 * EMB) /* 3072 */

// Scratch (no cudaMalloc allowed) — referenced directly as device globals.
__device__ float g_qkv[BATCH * S_LEN * QKV_F];   // [B, S, 3E] == per-(b,h) contiguous [2048,192]
__device__ float g_ctx[BATCH * S_LEN * EMB];     // [B, S, E] (head-transposed layout)

// ---------------------------------------------------------------------------
// Shared GEMM tile body: C[M,N] = A[M,K] @ B[N,K]^T + bias[N]
// 128x128 tile, BK=8, 256 threads, 8x8 per thread (split-tile 4+4 mapping).
// ---------------------------------------------------------------------------
__device__ __forceinline__ void gemm_nt_body(const float* __restrict__ A,
                                             const float* __restrict__ B,
                                             const float* __restrict__ bias,
                                             float* __restrict__ C,
                                             int M, int N, int K) {
    __shared__ float As[8][128];
    __shared__ float Bs[8][128];

    const int tid = threadIdx.x;
    const int tx = tid & 15;
    const int ty = tid >> 4;
    const int m0 = blockIdx.y * 128;
    const int n0 = blockIdx.x * 128;
    const int lm = tid >> 1;
    const int lk = (tid & 1) * 4;

    const float* Ap = A + (size_t)(m0 + lm) * K + lk;
    const float* Bp = B + (size_t)(n0 + lm) * K + lk;

    float acc[8][8];
#pragma unroll
    for (int i = 0; i < 8; i++)
#pragma unroll
        for (int j = 0; j < 8; j++) acc[i][j] = 0.0f;

    for (int k0 = 0; k0 < K; k0 += 8) {
        float4 av = *(const float4*)(Ap + k0);
        float4 bv = *(const float4*)(Bp + k0);
        __syncthreads();
        As[lk + 0][lm] = av.x; As[lk + 1][lm] = av.y;
        As[lk + 2][lm] = av.z; As[lk + 3][lm] = av.w;
        Bs[lk + 0][lm] = bv.x; Bs[lk + 1][lm] = bv.y;
        Bs[lk + 2][lm] = bv.z; Bs[lk + 3][lm] = bv.w;
        __syncthreads();

#pragma unroll
        for (int k = 0; k < 8; k++) {
            float4 a0 = *(const float4*)&As[k][ty * 4];
            float4 a1 = *(const float4*)&As[k][64 + ty * 4];
            float4 b0 = *(const float4*)&Bs[k][tx * 4];
            float4 b1 = *(const float4*)&Bs[k][64 + tx * 4];
            float a[8] = {a0.x, a0.y, a0.z, a0.w, a1.x, a1.y, a1.z, a1.w};
            float b[8] = {b0.x, b0.y, b0.z, b0.w, b1.x, b1.y, b1.z, b1.w};
#pragma unroll
            for (int i = 0; i < 8; i++)
#pragma unroll
                for (int j = 0; j < 8; j++) acc[i][j] += a[i] * b[j];
        }
    }

#pragma unroll
    for (int ih = 0; ih < 2; ih++) {
#pragma unroll
        for (int i = 0; i < 4; i++) {
            int row = m0 + ih * 64 + ty * 4 + i;
#pragma unroll
            for (int jh = 0; jh < 2; jh++) {
                int col = n0 + jh * 64 + tx * 4;
                float4 r;
                r.x = acc[ih * 4 + i][jh * 4 + 0] + bias[col + 0];
                r.y = acc[ih * 4 + i][jh * 4 + 1] + bias[col + 1];
                r.z = acc[ih * 4 + i][jh * 4 + 2] + bias[col + 2];
                r.w = acc[ih * 4 + i][jh * 4 + 3] + bias[col + 3];
                *(float4*)&C[(size_t)row * N + col] = r;
            }
        }
    }
}

__global__ __launch_bounds__(256) void gemm_nt_qkv(const float* __restrict__ A,
                                                   const float* __restrict__ B,
                                                   const float* __restrict__ bias,
                                                   int M, int N, int K) {
    gemm_nt_body(A, B, bias, g_qkv, M, N, K);
}

__global__ __launch_bounds__(256) void gemm_nt_out(const float* __restrict__ B,
                                                   const float* __restrict__ bias,
                                                   float* __restrict__ C,
                                                   int M, int N, int K) {
    gemm_nt_body(g_ctx, B, bias, C, M, N, K);
}

// ---------------------------------------------------------------------------
// Flash attention, fp32. One block = 64 query rows of one (b,h).
// Per-(b,h) QKV block: contiguous [2048, 192]; Q=cols 0:64, K=64:128, V=128:192.
// smem pitch 65 keeps all scalar accesses <=2-way bank-conflicted.
// ---------------------------------------------------------------------------
#define PITCH 65

__device__ __forceinline__ float rmax16(float v) {
    v = fmaxf(v, __shfl_xor_sync(0xffffffffu, v, 1));
    v = fmaxf(v, __shfl_xor_sync(0xffffffffu, v, 2));
    v = fmaxf(v, __shfl_xor_sync(0xffffffffu, v, 4));
    v = fmaxf(v, __shfl_xor_sync(0xffffffffu, v, 8));
    return v;
}
__device__ __forceinline__ float rsum16(float v) {
    v += __shfl_xor_sync(0xffffffffu, v, 1);
    v += __shfl_xor_sync(0xffffffffu, v, 2);
    v += __shfl_xor_sync(0xffffffffu, v, 4);
    v += __shfl_xor_sync(0xffffffffu, v, 8);
    return v;
}

__global__ __launch_bounds__(256) void attn_kernel() {
    extern __shared__ float sm[];
    float* Qt = sm;                    // [64 k][PITCH] k-major (pre-scaled by 1/8)
    float* Kt = Qt + 64 * PITCH;       // [64 k][PITCH] k-major
    float* Vs = Kt + 64 * PITCH;       // [64 c][PITCH] row-major
    float* Pt = Vs + 64 * PITCH;       // [64 c][PITCH] c-major

    const int tid = threadIdx.x;
    const int tx = tid & 15;
    const int ty = tid >> 4;
    const int q0 = blockIdx.x * 64;
    const int h = blockIdx.y;
    const int b = blockIdx.z;
    const float* qkv = g_qkv + (size_t)(b * HEADS + h) * (S_LEN * 3 * HDIM);

    // Load Q (transposed, pre-scaled by 1/sqrt(hd) = 0.125)
#pragma unroll
    for (int it = 0; it < 4; it++) {
        int idx = tid + it * 256;
        int r = idx >> 4, dg = idx & 15;
        float4 v = *(const float4*)(qkv + (size_t)(q0 + r) * 192 + dg * 4);
        Qt[(dg * 4 + 0) * PITCH + r] = v.x * 0.125f;
        Qt[(dg * 4 + 1) * PITCH + r] = v.y * 0.125f;
        Qt[(dg * 4 + 2) * PITCH + r] = v.z * 0.125f;
        Qt[(dg * 4 + 3) * PITCH + r] = v.w * 0.125f;
    }

    float m_run[4], l_run[4], o[4][4];
#pragma unroll
    for (int i = 0; i < 4; i++) {
        m_run[i] = -1e30f;
        l_run[i] = 0.0f;
#pragma unroll
        for (int j = 0; j < 4; j++) o[i][j] = 0.0f;
    }

    for (int c0 = 0; c0 < S_LEN; c0 += 64) {
#pragma unroll
        for (int it = 0; it < 4; it++) {
            int idx = tid + it * 256;
            int r = idx >> 4, dg = idx & 15;
            const float* base = qkv + (size_t)(c0 + r) * 192 + dg * 4;
            float4 kv = *(const float4*)(base + 64);
            float4 vv = *(const float4*)(base + 128);
            Kt[(dg * 4 + 0) * PITCH + r] = kv.x;
            Kt[(dg * 4 + 1) * PITCH + r] = kv.y;
            Kt[(dg * 4 + 2) * PITCH + r] = kv.z;
            Kt[(dg * 4 + 3) * PITCH + r] = kv.w;
            Vs[r * PITCH + dg * 4 + 0] = vv.x;
            Vs[r * PITCH + dg * 4 + 1] = vv.y;
            Vs[r * PITCH + dg * 4 + 2] = vv.z;
            Vs[r * PITCH + dg * 4 + 3] = vv.w;
        }
        __syncthreads();

        float s[4][4];
#pragma unroll
        for (int i = 0; i < 4; i++)
#pragma unroll
            for (int j = 0; j < 4; j++) s[i][j] = 0.0f;

#pragma unroll 8
        for (int k = 0; k < 64; k++) {
            float a0 = Qt[k * PITCH + ty * 4 + 0];
            float a1 = Qt[k * PITCH + ty * 4 + 1];
            float a2 = Qt[k * PITCH + ty * 4 + 2];
            float a3 = Qt[k * PITCH + ty * 4 + 3];
            float c0v = Kt[k * PITCH + tx * 4 + 0];
            float c1v = Kt[k * PITCH + tx * 4 + 1];
            float c2v = Kt[k * PITCH + tx * 4 + 2];
            float c3v = Kt[k * PITCH + tx * 4 + 3];
            s[0][0] += a0 * c0v; s[0][1] += a0 * c1v; s[0][2] += a0 * c2v; s[0][3] += a0 * c3v;
            s[1][0] += a1 * c0v; s[1][1] += a1 * c1v; s[1][2] += a1 * c2v; s[1][3] += a1 * c3v;
            s[2][0] += a2 * c0v; s[2][1] += a2 * c1v; s[2][2] += a2 * c2v; s[2][3] += a2 * c3v;
            s[3][0] += a3 * c0v; s[3][1] += a3 * c1v; s[3][2] += a3 * c2v; s[3][3] += a3 * c3v;
        }

#pragma unroll
        for (int i = 0; i < 4; i++) {
            float rm = fmaxf(fmaxf(s[i][0], s[i][1]), fmaxf(s[i][2], s[i][3]));
            rm = rmax16(rm);
            float newm = fmaxf(m_run[i], rm);
            float alpha = __expf(m_run[i] - newm);
            m_run[i] = newm;
            float rs = 0.0f;
#pragma unroll
            for (int j = 0; j < 4; j++) {
                s[i][j] = __expf(s[i][j] - newm);
                rs += s[i][j];
            }
            rs = rsum16(rs);
            l_run[i] = l_run[i] * alpha + rs;
#pragma unroll
            for (int j = 0; j < 4; j++) o[i][j] *= alpha;
        }

#pragma unroll
        for (int j = 0; j < 4; j++)
#pragma unroll
            for (int i = 0; i < 4; i++)
                Pt[(tx * 4 + j) * PITCH + ty * 4 + i] = s[i][j];
        __syncthreads();

#pragma unroll 8
        for (int c = 0; c < 64; c++) {
            float p0 = Pt[c * PITCH + ty * 4 + 0];
            float p1 = Pt[c * PITCH + ty * 4 + 1];
            float p2 = Pt[c * PITCH + ty * 4 + 2];
            float p3 = Pt[c * PITCH + ty * 4 + 3];
            float v0 = Vs[c * PITCH + tx * 4 + 0];
            float v1 = Vs[c * PITCH + tx * 4 + 1];
            float v2 = Vs[c * PITCH + tx * 4 + 2];
            float v3 = Vs[c * PITCH + tx * 4 + 3];
            o[0][0] += p0 * v0; o[0][1] += p0 * v1; o[0][2] += p0 * v2; o[0][3] += p0 * v3;
            o[1][0] += p1 * v0; o[1][1] += p1 * v1; o[1][2] += p1 * v2; o[1][3] += p1 * v3;
            o[2][0] += p2 * v0; o[2][1] += p2 * v1; o[2][2] += p2 * v2; o[2][3] += p2 * v3;
            o[3][0] += p3 * v0; o[3][1] += p3 * v1; o[3][2] += p3 * v2; o[3][3] += p3 * v3;
        }
        __syncthreads();
    }

    float* outp = g_ctx + ((size_t)b * S_LEN + q0) * EMB + h * HDIM;
#pragma unroll
    for (int i = 0; i < 4; i++) {
        float inv = 1.0f / l_run[i];
        float4 r;
        r.x = o[i][0] * inv; r.y = o[i][1] * inv;
        r.z = o[i][2] * inv; r.w = o[i][3] * inv;
        *(float4*)&outp[(size_t)(ty * 4 + i) * EMB + tx * 4] = r;
    }
}

// ---------------------------------------------------------------------------
extern "C" void kernel_launch(void* const* d_in, const int* in_sizes, int n_in,
                              void* d_out, int out_size) {
    const float* x     = (const float*)d_in[0];   // [B,S,E]
    const float* W_qkv = (const float*)d_in[1];   // [3E,E]
    const float* b_qkv = (const float*)d_in[2];   // [3E]
    const float* W_out = (const float*)d_in[3];   // [E,E]
    const float* b_out = (const float*)d_in[4];   // [E]
    float* out = (float*)d_out;

    // 1) qkv = x @ W_qkv^T + b_qkv   [4096, 3072] -> g_qkv
    {
        dim3 grid(QKV_F / 128, (BATCH * S_LEN) / 128);
        gemm_nt_qkv<<<grid, 256>>>(x, W_qkv, b_qkv, BATCH * S_LEN, QKV_F, EMB);
    }

    // 2) flash attention per (b,h): g_qkv -> g_ctx (head-transposed)
    {
        int smem = 4 * 64 * PITCH * (int)sizeof(float);  // 66,560 B
        cudaFuncSetAttribute(attn_kernel, cudaFuncAttributeMaxDynamicSharedMemorySize, smem);
        dim3 grid(S_LEN / 64, HEADS, BATCH);
        attn_kernel<<<grid, 256, smem>>>();
    }

    // 3) out = g_ctx @ W_out^T + b_out   [4096, 1024]
    {
        dim3 grid(EMB / 128, (BATCH * S_LEN) / 128);
        gemm_nt_out<<<grid, 256>>>(W_out, b_out, out, BATCH * S_LEN, EMB, EMB);
    }
}

// round 3
// speedup vs baseline: 2.7648x; 2.7648x over previous
#include <cuda_runtime.h>
#include <cstdint>

#define S_LEN 2048
#define EMB 1024
#define HEADS 16
#define HDIM 64
#define BATCH 2
#define QKV_F 3072

// Scratch (no cudaMalloc allowed)
__device__ float g_qkv[BATCH * S_LEN * QKV_F];   // [B,S,3E]: per-(b,h) contiguous [2048,192]
__device__ float g_ctx[BATCH * S_LEN * EMB];     // [B,S,E] head-transposed

__device__ __forceinline__ uint32_t f2tf(float f) {
    uint32_t u; asm("cvt.rna.tf32.f32 %0, %1;" : "=r"(u) : "f"(f)); return u;
}

__device__ __forceinline__ void mma8(float* c, const uint32_t* a, uint32_t b0, uint32_t b1) {
    asm volatile(
        "mma.sync.aligned.m16n8k8.row.col.f32.tf32.tf32.f32 "
        "{%0,%1,%2,%3}, {%4,%5,%6,%7}, {%8,%9}, {%0,%1,%2,%3};"
        : "+f"(c[0]), "+f"(c[1]), "+f"(c[2]), "+f"(c[3])
        : "r"(a[0]), "r"(a[1]), "r"(a[2]), "r"(a[3]), "r"(b0), "r"(b1));
}

// ---------------------------------------------------------------------------
// tf32 tensor-core GEMM: C[M,N] = A[M,K] @ B[N,K]^T + bias[N]
// 128x128 tile, BK=16, 256 thr (8 warps as 2Mx4N, warp tile 64x32).
// smem pitch 20 words -> conflict-free 8x4 fragment loads.
// ---------------------------------------------------------------------------
#define GP 20
#define GEMM_SMEM (2 * 2 * 128 * GP * 4)

__device__ __forceinline__ void gemm_tc_body(const float* __restrict__ A,
                                             const float* __restrict__ B,
                                             const float* __restrict__ bias,
                                             float* __restrict__ C,
                                             int M, int N, int K) {
    extern __shared__ uint32_t sh[];
    uint32_t* As = sh;                 // [2][128*GP]
    uint32_t* Bs = sh + 2 * 128 * GP;  // [2][128*GP]

    const int tid = threadIdx.x;
    const int lane = tid & 31;
    const int wid = tid >> 5;
    const int wm = wid >> 2;           // 0..1
    const int wn = wid & 3;            // 0..3
    const int m0 = blockIdx.y * 128;
    const int n0 = blockIdx.x * 128;
    const int lq = lane >> 2;          // 0..7
    const int lr = lane & 3;           // 0..3

    float acc[4][4][4];
#pragma unroll
    for (int mt = 0; mt < 4; mt++)
#pragma unroll
        for (int nt = 0; nt < 4; nt++)
#pragma unroll
            for (int i = 0; i < 4; i++) acc[mt][nt][i] = 0.0f;

    // tile 0 -> smem buf 0
#pragma unroll
    for (int i = 0; i < 2; i++) {
        int idx = tid + i * 256;         // 0..511
        int r = idx >> 2, c4 = idx & 3;  // r 0..127, c4 0..3
        float4 av = *(const float4*)(A + (size_t)(m0 + r) * K + c4 * 4);
        float4 bv = *(const float4*)(B + (size_t)(n0 + r) * K + c4 * 4);
        uint4 at = {f2tf(av.x), f2tf(av.y), f2tf(av.z), f2tf(av.w)};
        uint4 bt = {f2tf(bv.x), f2tf(bv.y), f2tf(bv.z), f2tf(bv.w)};
        *(uint4*)&As[r * GP + c4 * 4] = at;
        *(uint4*)&Bs[r * GP + c4 * 4] = bt;
    }
    __syncthreads();

    const int kiters = K >> 4;
    for (int it = 0; it < kiters; it++) {
        const int buf = it & 1;
        const uint32_t* Ab = As + buf * 128 * GP;
        const uint32_t* Bb = Bs + buf * 128 * GP;

        float4 pa[2], pb[2];
        if (it + 1 < kiters) {
            int k0 = (it + 1) * 16;
#pragma unroll
            for (int i = 0; i < 2; i++) {
                int idx = tid + i * 256;
                int r = idx >> 2, c4 = idx & 3;
                pa[i] = *(const float4*)(A + (size_t)(m0 + r) * K + k0 + c4 * 4);
                pb[i] = *(const float4*)(B + (size_t)(n0 + r) * K + k0 + c4 * 4);
            }
        }

#pragma unroll
        for (int ks = 0; ks < 2; ks++) {
            uint32_t bfr[4][2];
#pragma unroll
            for (int nt = 0; nt < 4; nt++) {
                int n = wn * 32 + nt * 8 + lq;
                int k = ks * 8 + lr;
                bfr[nt][0] = Bb[n * GP + k];
                bfr[nt][1] = Bb[n * GP + k + 4];
            }
#pragma unroll
            for (int mt = 0; mt < 4; mt++) {
                int r = wm * 64 + mt * 16 + lq;
                int k = ks * 8 + lr;
                uint32_t a[4];
                a[0] = Ab[r * GP + k];
                a[1] = Ab[(r + 8) * GP + k];
                a[2] = Ab[r * GP + k + 4];
                a[3] = Ab[(r + 8) * GP + k + 4];
#pragma unroll
                for (int nt = 0; nt < 4; nt++)
                    mma8(acc[mt][nt], a, bfr[nt][0], bfr[nt][1]);
            }
        }

        if (it + 1 < kiters) {
            uint32_t* Aw = As + (buf ^ 1) * 128 * GP;
            uint32_t* Bw = Bs + (buf ^ 1) * 128 * GP;
#pragma unroll
            for (int i = 0; i < 2; i++) {
                int idx = tid + i * 256;
                int r = idx >> 2, c4 = idx & 3;
                uint4 at = {f2tf(pa[i].x), f2tf(pa[i].y), f2tf(pa[i].z), f2tf(pa[i].w)};
                uint4 bt = {f2tf(pb[i].x), f2tf(pb[i].y), f2tf(pb[i].z), f2tf(pb[i].w)};
                *(uint4*)&Aw[r * GP + c4 * 4] = at;
                *(uint4*)&Bw[r * GP + c4 * 4] = bt;
            }
        }
        __syncthreads();
    }

    // epilogue + bias
#pragma unroll
    for (int mt = 0; mt < 4; mt++) {
        int row = m0 + wm * 64 + mt * 16 + lq;
#pragma unroll
        for (int nt = 0; nt < 4; nt++) {
            int col = n0 + wn * 32 + nt * 8 + 2 * lr;
            float2 bv = *(const float2*)&bias[col];
            float2 v0 = {acc[mt][nt][0] + bv.x, acc[mt][nt][1] + bv.y};
            float2 v1 = {acc[mt][nt][2] + bv.x, acc[mt][nt][3] + bv.y};
            *(float2*)&C[(size_t)row * N + col] = v0;
            *(float2*)&C[(size_t)(row + 8) * N + col] = v1;
        }
    }
}

__global__ __launch_bounds__(256, 2) void gemm_tc_qkv(const float* __restrict__ A,
                                                      const float* __restrict__ B,
                                                      const float* __restrict__ bias,
                                                      int M, int N, int K) {
    gemm_tc_body(A, B, bias, g_qkv, M, N, K);
}

__global__ __launch_bounds__(256, 2) void gemm_tc_out(const float* __restrict__ B,
                                                      const float* __restrict__ bias,
                                                      float* __restrict__ C,
                                                      int M, int N, int K) {
    gemm_tc_body(g_ctx, B, bias, C, M, N, K);
}

// ---------------------------------------------------------------------------
// Flash attention with tf32 mma. Block = 128 q rows of one (b,h), 8 warps,
// each warp owns a 16-row q band (softmax stays warp-local). kv tile = 64.
// smem pitch 68 words (== 4 mod 32) -> conflict-free fragment loads.
// ---------------------------------------------------------------------------
#define AP 68
#define ATTN_SMEM ((128 * AP + 64 * AP + 64 * AP + 128 * AP) * 4)

__global__ __launch_bounds__(256, 2) void attn_tc_kernel() {
    extern __shared__ uint32_t sh[];
    uint32_t* Qs = sh;                   // [128][AP] (q, hd) pre-scaled by 0.125
    uint32_t* Ks = Qs + 128 * AP;        // [64][AP]  (kv, hd)
    uint32_t* Vt = Ks + 64 * AP;         // [64][AP]  (hd, kv)  transposed
    uint32_t* Ps = Vt + 64 * AP;         // [128][AP] (q, kv)

    const int tid = threadIdx.x;
    const int lane = tid & 31;
    const int wq = tid >> 5;             // warp id -> q band [wq*16, wq*16+16)
    const int lq = lane >> 2;            // 0..7
    const int lr = lane & 3;             // 0..3
    const int q0 = blockIdx.x * 128;
    const int h = blockIdx.y;
    const int b = blockIdx.z;
    const float* qkv = g_qkv + (size_t)(b * HEADS + h) * (S_LEN * 3 * HDIM);

    // Load Q (pre-scaled by 1/sqrt(64))
#pragma unroll
    for (int i = 0; i < 8; i++) {
        int idx = tid + i * 256;          // 0..2047
        int r = idx >> 4, dg = idx & 15;  // r 0..127, dg 0..15
        float4 v = *(const float4*)(qkv + (size_t)(q0 + r) * 192 + dg * 4);
        uint4 t = {f2tf(v.x * 0.125f), f2tf(v.y * 0.125f),
                   f2tf(v.z * 0.125f), f2tf(v.w * 0.125f)};
        *(uint4*)&Qs[r * AP + dg * 4] = t;
    }

    float o[8][4];
#pragma unroll
    for (int nt = 0; nt < 8; nt++)
#pragma unroll
        for (int i = 0; i < 4; i++) o[nt][i] = 0.0f;
    float m0r = -1e30f, m1r = -1e30f, l0r = 0.0f, l1r = 0.0f;

    for (int c0 = 0; c0 < S_LEN; c0 += 64) {
        // Load K (straight) and V (transposed)
#pragma unroll
        for (int i = 0; i < 4; i++) {
            int idx = tid + i * 256;          // 0..1023
            int r = idx >> 4, dg = idx & 15;  // r 0..63
            const float* base = qkv + (size_t)(c0 + r) * 192 + dg * 4;
            float4 kv = *(const float4*)(base + 64);
            float4 vv = *(const float4*)(base + 128);
            uint4 kt = {f2tf(kv.x), f2tf(kv.y), f2tf(kv.z), f2tf(kv.w)};
            *(uint4*)&Ks[r * AP + dg * 4] = kt;
            Vt[(dg * 4 + 0) * AP + r] = f2tf(vv.x);
            Vt[(dg * 4 + 1) * AP + r] = f2tf(vv.y);
            Vt[(dg * 4 + 2) * AP + r] = f2tf(vv.z);
            Vt[(dg * 4 + 3) * AP + r] = f2tf(vv.w);
        }
        __syncthreads();

        // S = Q @ K^T : warp computes [16 x 64]
        float s[8][4];
#pragma unroll
        for (int nt = 0; nt < 8; nt++)
#pragma unroll
            for (int i = 0; i < 4; i++) s[nt][i] = 0.0f;

#pragma unroll
        for (int ks = 0; ks < 8; ks++) {
            int r = wq * 16 + lq;
            int k = ks * 8 + lr;
            uint32_t a[4];
            a[0] = Qs[r * AP + k];
            a[1] = Qs[(r + 8) * AP + k];
            a[2] = Qs[r * AP + k + 4];
            a[3] = Qs[(r + 8) * AP + k + 4];
#pragma unroll
            for (int nt = 0; nt < 8; nt++) {
                int n = nt * 8 + lq;
                uint32_t b0 = Ks[n * AP + k];
                uint32_t b1 = Ks[n * AP + k + 4];
                mma8(s[nt], a, b0, b1);
            }
        }

        // Online softmax: thread owns cols of rows lq and lq+8 in warp band.
        float rm0 = -1e30f, rm1 = -1e30f;
#pragma unroll
        for (int nt = 0; nt < 8; nt++) {
            rm0 = fmaxf(rm0, fmaxf(s[nt][0], s[nt][1]));
            rm1 = fmaxf(rm1, fmaxf(s[nt][2], s[nt][3]));
        }
        rm0 = fmaxf(rm0, __shfl_xor_sync(0xffffffffu, rm0, 1));
        rm0 = fmaxf(rm0, __shfl_xor_sync(0xffffffffu, rm0, 2));
        rm1 = fmaxf(rm1, __shfl_xor_sync(0xffffffffu, rm1, 1));
        rm1 = fmaxf(rm1, __shfl_xor_sync(0xffffffffu, rm1, 2));

        float nm0 = fmaxf(m0r, rm0), nm1 = fmaxf(m1r, rm1);
        float al0 = __expf(m0r - nm0), al1 = __expf(m1r - nm1);
        m0r = nm0; m1r = nm1;

        float rs0 = 0.0f, rs1 = 0.0f;
#pragma unroll
        for (int nt = 0; nt < 8; nt++) {
            s[nt][0] = __expf(s[nt][0] - nm0);
            s[nt][1] = __expf(s[nt][1] - nm0);
            s[nt][2] = __expf(s[nt][2] - nm1);
            s[nt][3] = __expf(s[nt][3] - nm1);
            rs0 += s[nt][0] + s[nt][1];
            rs1 += s[nt][2] + s[nt][3];
        }
        rs0 += __shfl_xor_sync(0xffffffffu, rs0, 1);
        rs0 += __shfl_xor_sync(0xffffffffu, rs0, 2);
        rs1 += __shfl_xor_sync(0xffffffffu, rs1, 1);
        rs1 += __shfl_xor_sync(0xffffffffu, rs1, 2);
        l0r = l0r * al0 + rs0;
        l1r = l1r * al1 + rs1;
#pragma unroll
        for (int nt = 0; nt < 8; nt++) {
            o[nt][0] *= al0; o[nt][1] *= al0;
            o[nt][2] *= al1; o[nt][3] *= al1;
        }

        // P -> smem (warp-private rows)
        {
            int r = wq * 16 + lq;
#pragma unroll
            for (int nt = 0; nt < 8; nt++) {
                int col = nt * 8 + 2 * lr;
                uint2 p0 = {f2tf(s[nt][0]), f2tf(s[nt][1])};
                uint2 p1 = {f2tf(s[nt][2]), f2tf(s[nt][3])};
                *(uint2*)&Ps[r * AP + col] = p0;
                *(uint2*)&Ps[(r + 8) * AP + col] = p1;
            }
        }
        __syncwarp();

        // O += P @ V : A from Ps (q, kv), B from Vt (hd-major, kv contiguous)
#pragma unroll
        for (int ks = 0; ks < 8; ks++) {
            int r = wq * 16 + lq;
            int k = ks * 8 + lr;
            uint32_t a[4];
            a[0] = Ps[r * AP + k];
            a[1] = Ps[(r + 8) * AP + k];
            a[2] = Ps[r * AP + k + 4];
            a[3] = Ps[(r + 8) * AP + k + 4];
#pragma unroll
            for (int nt = 0; nt < 8; nt++) {
                int n = nt * 8 + lq;
                uint32_t b0 = Vt[n * AP + k];
                uint32_t b1 = Vt[n * AP + k + 4];
                mma8(o[nt], a, b0, b1);
            }
        }
        __syncthreads();   // K/V/P buffers free for next tile
    }

    // Write ctx[b, q, h*64+d] (head-transposed), normalize by l.
    float inv0 = 1.0f / l0r, inv1 = 1.0f / l1r;
    int qrow = q0 + wq * 16 + lq;
    float* outp = g_ctx + ((size_t)b * S_LEN + qrow) * EMB + h * HDIM;
#pragma unroll
    for (int nt = 0; nt < 8; nt++) {
        int col = nt * 8 + 2 * lr;
        float2 v0 = {o[nt][0] * inv0, o[nt][1] * inv0};
        float2 v1 = {o[nt][2] * inv1, o[nt][3] * inv1};
        *(float2*)&outp[col] = v0;
        *(float2*)&outp[8 * EMB + col] = v1;
    }
}

// ---------------------------------------------------------------------------
extern "C" void kernel_launch(void* const* d_in, const int* in_sizes, int n_in,
                              void* d_out, int out_size) {
    const float* x     = (const float*)d_in[0];
    const float* W_qkv = (const float*)d_in[1];
    const float* b_qkv = (const float*)d_in[2];
    const float* W_out = (const float*)d_in[3];
    const float* b_out = (const float*)d_in[4];
    float* out = (float*)d_out;

    cudaFuncSetAttribute(gemm_tc_qkv, cudaFuncAttributeMaxDynamicSharedMemorySize, GEMM_SMEM);
    cudaFuncSetAttribute(gemm_tc_out, cudaFuncAttributeMaxDynamicSharedMemorySize, GEMM_SMEM);
    cudaFuncSetAttribute(attn_tc_kernel, cudaFuncAttributeMaxDynamicSharedMemorySize, ATTN_SMEM);

    // 1) qkv = x @ W_qkv^T + b_qkv  [4096, 3072]
    {
        dim3 grid(QKV_F / 128, (BATCH * S_LEN) / 128);
        gemm_tc_qkv<<<grid, 256, GEMM_SMEM>>>(x, W_qkv, b_qkv, BATCH * S_LEN, QKV_F, EMB);
    }
    // 2) flash attention
    {
        dim3 grid(S_LEN / 128, HEADS, BATCH);
        attn_tc_kernel<<<grid, 256, ATTN_SMEM>>>();
    }
    // 3) out = ctx @ W_out^T + b_out  [4096, 1024]
    {
        dim3 grid(EMB / 128, (BATCH * S_LEN) / 128);
        gemm_tc_out<<<grid, 256, GEMM_SMEM>>>(W_out, b_out, out, BATCH * S_LEN, EMB, EMB);
    }
}

// round 4
// speedup vs baseline: 3.1177x; 1.1276x over previous
#include <cuda_runtime.h>
#include <cstdint>

#define S_LEN 2048
#define EMB 1024
#define HEADS 16
#define HDIM 64
#define BATCH 2
#define QKV_F 3072

// Scratch (no cudaMalloc allowed)
__device__ float g_qkv[BATCH * S_LEN * QKV_F];   // [B,S,3E]: per-(b,h) contiguous [2048,192]
__device__ float g_ctx[BATCH * S_LEN * EMB];     // [B,S,E] head-transposed

__device__ __forceinline__ uint32_t f2tf(float f) {
    uint32_t u; asm("cvt.rna.tf32.f32 %0, %1;" : "=r"(u) : "f"(f)); return u;
}

__device__ __forceinline__ void mma8(float* c, const uint32_t* a, uint32_t b0, uint32_t b1) {
    asm volatile(
        "mma.sync.aligned.m16n8k8.row.col.f32.tf32.tf32.f32 "
        "{%0,%1,%2,%3}, {%4,%5,%6,%7}, {%8,%9}, {%0,%1,%2,%3};"
        : "+f"(c[0]), "+f"(c[1]), "+f"(c[2]), "+f"(c[3])
        : "r"(a[0]), "r"(a[1]), "r"(a[2]), "r"(a[3]), "r"(b0), "r"(b1));
}

// ldmatrix x4 of b32 data (viewed as b16 8x8 matrices). One instr = 4 fragment regs.
__device__ __forceinline__ void ldsm4(uint32_t& r0, uint32_t& r1, uint32_t& r2, uint32_t& r3,
                                      const uint32_t* p) {
    uint32_t a = (uint32_t)__cvta_generic_to_shared(p);
    asm volatile("ldmatrix.sync.aligned.m8n8.x4.shared.b16 {%0,%1,%2,%3}, [%4];"
                 : "=r"(r0), "=r"(r1), "=r"(r2), "=r"(r3) : "r"(a));
}

// ---------------------------------------------------------------------------
// tf32 tensor-core GEMM: C[M,N] = A[M,K] @ B[N,K]^T + bias[N]
// 128x128 tile, BK=16, 256 thr (8 warps as 2Mx4N, warp tile 64x32).
// Fragment loads via ldmatrix.x4 (pitch 20 words -> conflict-free LDSM rows).
// ---------------------------------------------------------------------------
#define GP 20
#define GEMM_SMEM (2 * 2 * 128 * GP * 4)

__device__ __forceinline__ void gemm_tc_body(const float* __restrict__ A,
                                             const float* __restrict__ B,
                                             const float* __restrict__ bias,
                                             float* __restrict__ C,
                                             int M, int N, int K) {
    extern __shared__ uint32_t sh[];
    uint32_t* As = sh;                 // [2][128*GP]
    uint32_t* Bs = sh + 2 * 128 * GP;  // [2][128*GP]

    const int tid = threadIdx.x;
    const int lane = tid & 31;
    const int wid = tid >> 5;
    const int wm = wid >> 2;           // 0..1
    const int wn = wid & 3;            // 0..3
    const int m0 = blockIdx.y * 128;
    const int n0 = blockIdx.x * 128;
    const int lq = lane >> 2;          // 0..7
    const int lr = lane & 3;           // 0..3

    // ldmatrix lane-derived offsets
    const int a_row = lane & 15;                 // row within 16-row band
    const int a_kof = (lane >> 4) << 2;          // 0 or 4
    const int b_row = ((lane >> 4) << 3) + (lane & 7);  // row within 16-n band
    const int b_kof = ((lane >> 3) & 1) << 2;    // 0 or 4

    float acc[4][4][4];
#pragma unroll
    for (int mt = 0; mt < 4; mt++)
#pragma unroll
        for (int nt = 0; nt < 4; nt++)
#pragma unroll
            for (int i = 0; i < 4; i++) acc[mt][nt][i] = 0.0f;

    // tile 0 -> smem buf 0
#pragma unroll
    for (int i = 0; i < 2; i++) {
        int idx = tid + i * 256;
        int r = idx >> 2, c4 = idx & 3;
        float4 av = *(const float4*)(A + (size_t)(m0 + r) * K + c4 * 4);
        float4 bv = *(const float4*)(B + (size_t)(n0 + r) * K + c4 * 4);
        uint4 at = {f2tf(av.x), f2tf(av.y), f2tf(av.z), f2tf(av.w)};
        uint4 bt = {f2tf(bv.x), f2tf(bv.y), f2tf(bv.z), f2tf(bv.w)};
        *(uint4*)&As[r * GP + c4 * 4] = at;
        *(uint4*)&Bs[r * GP + c4 * 4] = bt;
    }
    __syncthreads();

    const int kiters = K >> 4;
    for (int it = 0; it < kiters; it++) {
        const int buf = it & 1;
        const uint32_t* Ab = As + buf * 128 * GP;
        const uint32_t* Bb = Bs + buf * 128 * GP;

        float4 pa[2], pb[2];
        if (it + 1 < kiters) {
            int k0 = (it + 1) * 16;
#pragma unroll
            for (int i = 0; i < 2; i++) {
                int idx = tid + i * 256;
                int r = idx >> 2, c4 = idx & 3;
                pa[i] = *(const float4*)(A + (size_t)(m0 + r) * K + k0 + c4 * 4);
                pb[i] = *(const float4*)(B + (size_t)(n0 + r) * K + k0 + c4 * 4);
            }
        }

#pragma unroll
        for (int ks = 0; ks < 2; ks++) {
            uint32_t bfr[4][2];
            // 2 ldsm.x4 load all four 8-col B fragments of the 32-wide warp band
#pragma unroll
            for (int ntp = 0; ntp < 2; ntp++) {
                const uint32_t* bp =
                    Bb + (wn * 32 + ntp * 16 + b_row) * GP + ks * 8 + b_kof;
                ldsm4(bfr[2 * ntp][0], bfr[2 * ntp][1],
                      bfr[2 * ntp + 1][0], bfr[2 * ntp + 1][1], bp);
            }
#pragma unroll
            for (int mt = 0; mt < 4; mt++) {
                const uint32_t* ap =
                    Ab + (wm * 64 + mt * 16 + a_row) * GP + ks * 8 + a_kof;
                uint32_t a[4];
                ldsm4(a[0], a[1], a[2], a[3], ap);
#pragma unroll
                for (int nt = 0; nt < 4; nt++)
                    mma8(acc[mt][nt], a, bfr[nt][0], bfr[nt][1]);
            }
        }

        if (it + 1 < kiters) {
            uint32_t* Aw = As + (buf ^ 1) * 128 * GP;
            uint32_t* Bw = Bs + (buf ^ 1) * 128 * GP;
#pragma unroll
            for (int i = 0; i < 2; i++) {
                int idx = tid + i * 256;
                int r = idx >> 2, c4 = idx & 3;
                uint4 at = {f2tf(pa[i].x), f2tf(pa[i].y), f2tf(pa[i].z), f2tf(pa[i].w)};
                uint4 bt = {f2tf(pb[i].x), f2tf(pb[i].y), f2tf(pb[i].z), f2tf(pb[i].w)};
                *(uint4*)&Aw[r * GP + c4 * 4] = at;
                *(uint4*)&Bw[r * GP + c4 * 4] = bt;
            }
        }
        __syncthreads();
    }

    // epilogue + bias
#pragma unroll
    for (int mt = 0; mt < 4; mt++) {
        int row = m0 + wm * 64 + mt * 16 + lq;
#pragma unroll
        for (int nt = 0; nt < 4; nt++) {
            int col = n0 + wn * 32 + nt * 8 + 2 * lr;
            float2 bv = *(const float2*)&bias[col];
            float2 v0 = {acc[mt][nt][0] + bv.x, acc[mt][nt][1] + bv.y};
            float2 v1 = {acc[mt][nt][2] + bv.x, acc[mt][nt][3] + bv.y};
            *(float2*)&C[(size_t)row * N + col] = v0;
            *(float2*)&C[(size_t)(row + 8) * N + col] = v1;
        }
    }
}

__global__ __launch_bounds__(256, 2) void gemm_tc_qkv(const float* __restrict__ A,
                                                      const float* __restrict__ B,
                                                      const float* __restrict__ bias,
                                                      int M, int N, int K) {
    gemm_tc_body(A, B, bias, g_qkv, M, N, K);
}

__global__ __launch_bounds__(256, 2) void gemm_tc_out(const float* __restrict__ B,
                                                      const float* __restrict__ bias,
                                                      float* __restrict__ C,
                                                      int M, int N, int K) {
    gemm_tc_body(g_ctx, B, bias, C, M, N, K);
}

// ---------------------------------------------------------------------------
// Flash attention with tf32 mma + ldmatrix. Block = 128 q rows, 8 warps, each
// warp owns a 16-row q band. kv tile = 64. Pitch 68 (==4 mod 32): LDSM-clean.
// ---------------------------------------------------------------------------
#define AP 68
#define ATTN_SMEM ((128 * AP + 64 * AP + 64 * AP + 128 * AP) * 4)

__global__ __launch_bounds__(256, 2) void attn_tc_kernel() {
    extern __shared__ uint32_t sh[];
    uint32_t* Qs = sh;                   // [128][AP] (q, hd) pre-scaled by 0.125
    uint32_t* Ks = Qs + 128 * AP;        // [64][AP]  (kv, hd)
    uint32_t* Vt = Ks + 64 * AP;         // [64][AP]  (hd, kv) transposed
    uint32_t* Ps = Vt + 64 * AP;         // [128][AP] (q, kv)

    const int tid = threadIdx.x;
    const int lane = tid & 31;
    const int wq = tid >> 5;
    const int lq = lane >> 2;
    const int lr = lane & 3;
    const int q0 = blockIdx.x * 128;
    const int h = blockIdx.y;
    const int b = blockIdx.z;
    const float* qkv = g_qkv + (size_t)(b * HEADS + h) * (S_LEN * 3 * HDIM);

    const int a_row = lane & 15;
    const int a_kof = (lane >> 4) << 2;
    const int b_row = ((lane >> 4) << 3) + (lane & 7);
    const int b_kof = ((lane >> 3) & 1) << 2;

    // Load Q (pre-scaled by 1/sqrt(64))
#pragma unroll
    for (int i = 0; i < 8; i++) {
        int idx = tid + i * 256;
        int r = idx >> 4, dg = idx & 15;
        float4 v = *(const float4*)(qkv + (size_t)(q0 + r) * 192 + dg * 4);
        uint4 t = {f2tf(v.x * 0.125f), f2tf(v.y * 0.125f),
                   f2tf(v.z * 0.125f), f2tf(v.w * 0.125f)};
        *(uint4*)&Qs[r * AP + dg * 4] = t;
    }

    float o[8][4];
#pragma unroll
    for (int nt = 0; nt < 8; nt++)
#pragma unroll
        for (int i = 0; i < 4; i++) o[nt][i] = 0.0f;
    float m0r = -1e30f, m1r = -1e30f, l0r = 0.0f, l1r = 0.0f;

    for (int c0 = 0; c0 < S_LEN; c0 += 64) {
        // Load K (straight) and V (transposed)
#pragma unroll
        for (int i = 0; i < 4; i++) {
            int idx = tid + i * 256;
            int r = idx >> 4, dg = idx & 15;
            const float* base = qkv + (size_t)(c0 + r) * 192 + dg * 4;
            float4 kv = *(const float4*)(base + 64);
            float4 vv = *(const float4*)(base + 128);
            uint4 kt = {f2tf(kv.x), f2tf(kv.y), f2tf(kv.z), f2tf(kv.w)};
            *(uint4*)&Ks[r * AP + dg * 4] = kt;
            Vt[(dg * 4 + 0) * AP + r] = f2tf(vv.x);
            Vt[(dg * 4 + 1) * AP + r] = f2tf(vv.y);
            Vt[(dg * 4 + 2) * AP + r] = f2tf(vv.z);
            Vt[(dg * 4 + 3) * AP + r] = f2tf(vv.w);
        }
        __syncthreads();

        // S = Q @ K^T : warp computes [16 x 64]
        float s[8][4];
#pragma unroll
        for (int nt = 0; nt < 8; nt++)
#pragma unroll
            for (int i = 0; i < 4; i++) s[nt][i] = 0.0f;

#pragma unroll
        for (int ks = 0; ks < 8; ks++) {
            uint32_t a[4];
            ldsm4(a[0], a[1], a[2], a[3],
                  Qs + (wq * 16 + a_row) * AP + ks * 8 + a_kof);
#pragma unroll
            for (int ntp = 0; ntp < 4; ntp++) {
                uint32_t b0a, b1a, b0b, b1b;
                ldsm4(b0a, b1a, b0b, b1b,
                      Ks + (ntp * 16 + b_row) * AP + ks * 8 + b_kof);
                mma8(s[2 * ntp], a, b0a, b1a);
                mma8(s[2 * ntp + 1], a, b0b, b1b);
            }
        }

        // Online softmax (rows lq and lq+8 of warp band)
        float rm0 = -1e30f, rm1 = -1e30f;
#pragma unroll
        for (int nt = 0; nt < 8; nt++) {
            rm0 = fmaxf(rm0, fmaxf(s[nt][0], s[nt][1]));
            rm1 = fmaxf(rm1, fmaxf(s[nt][2], s[nt][3]));
        }
        rm0 = fmaxf(rm0, __shfl_xor_sync(0xffffffffu, rm0, 1));
        rm0 = fmaxf(rm0, __shfl_xor_sync(0xffffffffu, rm0, 2));
        rm1 = fmaxf(rm1, __shfl_xor_sync(0xffffffffu, rm1, 1));
        rm1 = fmaxf(rm1, __shfl_xor_sync(0xffffffffu, rm1, 2));

        float nm0 = fmaxf(m0r, rm0), nm1 = fmaxf(m1r, rm1);
        float al0 = __expf(m0r - nm0), al1 = __expf(m1r - nm1);
        m0r = nm0; m1r = nm1;

        float rs0 = 0.0f, rs1 = 0.0f;
#pragma unroll
        for (int nt = 0; nt < 8; nt++) {
            s[nt][0] = __expf(s[nt][0] - nm0);
            s[nt][1] = __expf(s[nt][1] - nm0);
            s[nt][2] = __expf(s[nt][2] - nm1);
            s[nt][3] = __expf(s[nt][3] - nm1);
            rs0 += s[nt][0] + s[nt][1];
            rs1 += s[nt][2] + s[nt][3];
        }
        rs0 += __shfl_xor_sync(0xffffffffu, rs0, 1);
        rs0 += __shfl_xor_sync(0xffffffffu, rs0, 2);
        rs1 += __shfl_xor_sync(0xffffffffu, rs1, 1);
        rs1 += __shfl_xor_sync(0xffffffffu, rs1, 2);
        l0r = l0r * al0 + rs0;
        l1r = l1r * al1 + rs1;
#pragma unroll
        for (int nt = 0; nt < 8; nt++) {
            o[nt][0] *= al0; o[nt][1] *= al0;
            o[nt][2] *= al1; o[nt][3] *= al1;
        }

        // P -> smem (warp-private rows)
        {
            int r = wq * 16 + lq;
#pragma unroll
            for (int nt = 0; nt < 8; nt++) {
                int col = nt * 8 + 2 * lr;
                uint2 p0 = {f2tf(s[nt][0]), f2tf(s[nt][1])};
                uint2 p1 = {f2tf(s[nt][2]), f2tf(s[nt][3])};
                *(uint2*)&Ps[r * AP + col] = p0;
                *(uint2*)&Ps[(r + 8) * AP + col] = p1;
            }
        }
        __syncwarp();

        // O += P @ V
#pragma unroll
        for (int ks = 0; ks < 8; ks++) {
            uint32_t a[4];
            ldsm4(a[0], a[1], a[2], a[3],
                  Ps + (wq * 16 + a_row) * AP + ks * 8 + a_kof);
#pragma unroll
            for (int ntp = 0; ntp < 4; ntp++) {
                uint32_t b0a, b1a, b0b, b1b;
                ldsm4(b0a, b1a, b0b, b1b,
                      Vt + (ntp * 16 + b_row) * AP + ks * 8 + b_kof);
                mma8(o[2 * ntp], a, b0a, b1a);
                mma8(o[2 * ntp + 1], a, b0b, b1b);
            }
        }
        __syncthreads();
    }

    // Write ctx[b, q, h*64+d] (head-transposed), normalize by l.
    float inv0 = 1.0f / l0r, inv1 = 1.0f / l1r;
    int qrow = q0 + wq * 16 + lq;
    float* outp = g_ctx + ((size_t)b * S_LEN + qrow) * EMB + h * HDIM;
#pragma unroll
    for (int nt = 0; nt < 8; nt++) {
        int col = nt * 8 + 2 * lr;
        float2 v0 = {o[nt][0] * inv0, o[nt][1] * inv0};
        float2 v1 = {o[nt][2] * inv1, o[nt][3] * inv1};
        *(float2*)&outp[col] = v0;
        *(float2*)&outp[8 * EMB + col] = v1;
    }
}

// ---------------------------------------------------------------------------
extern "C" void kernel_launch(void* const* d_in, const int* in_sizes, int n_in,
                              void* d_out, int out_size) {
    const float* x     = (const float*)d_in[0];
    const float* W_qkv = (const float*)d_in[1];
    const float* b_qkv = (const float*)d_in[2];
    const float* W_out = (const float*)d_in[3];
    const float* b_out = (const float*)d_in[4];
    float* out = (float*)d_out;

    cudaFuncSetAttribute(gemm_tc_qkv, cudaFuncAttributeMaxDynamicSharedMemorySize, GEMM_SMEM);
    cudaFuncSetAttribute(gemm_tc_out, cudaFuncAttributeMaxDynamicSharedMemorySize, GEMM_SMEM);
    cudaFuncSetAttribute(attn_tc_kernel, cudaFuncAttributeMaxDynamicSharedMemorySize, ATTN_SMEM);

    {
        dim3 grid(QKV_F / 128, (BATCH * S_LEN) / 128);
        gemm_tc_qkv<<<grid, 256, GEMM_SMEM>>>(x, W_qkv, b_qkv, BATCH * S_LEN, QKV_F, EMB);
    }
    {
        dim3 grid(S_LEN / 128, HEADS, BATCH);
        attn_tc_kernel<<<grid, 256, ATTN_SMEM>>>();
    }
    {
        dim3 grid(EMB / 128, (BATCH * S_LEN) / 128);
        gemm_tc_out<<<grid, 256, GEMM_SMEM>>>(W_out, b_out, out, BATCH * S_LEN, EMB, EMB);
    }
}